// round 2
// baseline (speedup 1.0000x reference)
#include <cuda_runtime.h>
#include <math.h>

// Problem constants
#define NNODES 50000
#define NEDGES 800000
#define DD     128
#define EE     32
#define MSGD   128
#define K1     160   // D + E
#define LL     2
#define PP     2

// Tiling
#define TILE_E  64
#define KC      32
#define THREADS 256

// Padded shared strides (avoid bank conflicts: 160%32==0, 128%32==0)
#define SX_LD 164
#define SH_LD 132

// -------- scratch (allocation-free: __device__ globals) ----------
__device__ float g_stateA[NNODES * DD];
__device__ float g_stateB[NNODES * DD];
__device__ float g_msg[NNODES * MSGD];
__device__ float g_gi[NNODES * 3 * DD];
__device__ float g_gh[NNODES * 3 * DD];

// ---------------- fused edge kernel -------------------------------
// One CTA = 64 edges. Computes:
//   X = [state[src]-state[dst], edge_feat]                (smem, 64x160)
//   H = relu(X@W1 + b1); MSG = H@W2 + b2                  (smem)
//   H = relu(X@A1 + ab1); ATT = sigmoid(H@A2 + ab2)
//   atomicAdd(out_msg[dst], MSG * ATT)
// Register tile per thread: 4 edges x 8 cols.

__device__ __forceinline__ void mm_tile(const float* sIn, int ldIn, int kdim,
                                        const float* __restrict__ gW, float* sW,
                                        float acc[4][8], int tid, int tx, int ty)
{
#pragma unroll
    for (int m = 0; m < 4; m++)
#pragma unroll
        for (int n = 0; n < 8; n++) acc[m][n] = 0.f;

    for (int kc = 0; kc < kdim; kc += KC) {
        __syncthreads();  // protect sW reuse + orders producer writes
#pragma unroll
        for (int i = tid; i < KC * 128; i += THREADS)
            sW[i] = gW[(size_t)(kc + (i >> 7)) * 128 + (i & 127)];
        __syncthreads();
#pragma unroll 8
        for (int kk = 0; kk < KC; ++kk) {
            float a[4];
#pragma unroll
            for (int m = 0; m < 4; m++) a[m] = sIn[(ty * 4 + m) * ldIn + kc + kk];
            float4 bv0 = *(const float4*)&sW[kk * 128 + tx * 8];
            float4 bv1 = *(const float4*)&sW[kk * 128 + tx * 8 + 4];
            float b[8] = {bv0.x, bv0.y, bv0.z, bv0.w, bv1.x, bv1.y, bv1.z, bv1.w};
#pragma unroll
            for (int m = 0; m < 4; m++)
#pragma unroll
                for (int n = 0; n < 8; n++)
                    acc[m][n] = fmaf(a[m], b[n], acc[m][n]);
        }
    }
}

__global__ void __launch_bounds__(THREADS) edge_kernel(
    const float* __restrict__ state,
    const int* __restrict__ src, const int* __restrict__ dst,
    const float* __restrict__ edge_feat,
    const float* __restrict__ W1, const float* __restrict__ b1,
    const float* __restrict__ W2, const float* __restrict__ b2,
    const float* __restrict__ A1, const float* __restrict__ ab1,
    const float* __restrict__ A2, const float* __restrict__ ab2,
    float* __restrict__ out_msg)
{
    extern __shared__ float sm[];
    float* sX = sm;                            // TILE_E * SX_LD
    float* sH = sX + TILE_E * SX_LD;           // TILE_E * SH_LD
    float* sM = sH + TILE_E * SH_LD;           // TILE_E * SH_LD
    float* sW = sM + TILE_E * SH_LD;           // KC * 128
    __shared__ int sSrc[TILE_E], sDst[TILE_E];

    int tid = threadIdx.x;
    int tx = tid & 15;   // col group: j = tx*8 .. tx*8+7
    int ty = tid >> 4;   // edge group: e = ty*4 .. ty*4+3
    int e0 = blockIdx.x * TILE_E;

    if (tid < TILE_E) { sSrc[tid] = src[e0 + tid]; sDst[tid] = dst[e0 + tid]; }
    __syncthreads();

    // Gather edge_input
    for (int idx = tid; idx < TILE_E * K1; idx += THREADS) {
        int e = idx / K1, k = idx - e * K1;
        float v;
        if (k < DD)
            v = state[(size_t)sSrc[e] * DD + k] - state[(size_t)sDst[e] * DD + k];
        else
            v = edge_feat[(size_t)(e0 + e) * EE + (k - DD)];
        sX[e * SX_LD + k] = v;
    }
    // (mm_tile begins with __syncthreads)

    float acc[4][8];

    // H = relu(X @ W1 + b1)
    mm_tile(sX, SX_LD, K1, W1, sW, acc, tid, tx, ty);
#pragma unroll
    for (int n = 0; n < 8; n++) {
        float bb = __ldg(&b1[tx * 8 + n]);
#pragma unroll
        for (int m = 0; m < 4; m++) {
            float v = acc[m][n] + bb;
            sH[(ty * 4 + m) * SH_LD + tx * 8 + n] = v > 0.f ? v : 0.f;
        }
    }

    // MSG = H @ W2 + b2
    mm_tile(sH, SH_LD, MSGD, W2, sW, acc, tid, tx, ty);
#pragma unroll
    for (int n = 0; n < 8; n++) {
        float bb = __ldg(&b2[tx * 8 + n]);
#pragma unroll
        for (int m = 0; m < 4; m++)
            sM[(ty * 4 + m) * SH_LD + tx * 8 + n] = acc[m][n] + bb;
    }

    // H = relu(X @ A1 + ab1)   (overwrites sH; safe via mm_tile's chunk syncs)
    mm_tile(sX, SX_LD, K1, A1, sW, acc, tid, tx, ty);
#pragma unroll
    for (int n = 0; n < 8; n++) {
        float bb = __ldg(&ab1[tx * 8 + n]);
#pragma unroll
        for (int m = 0; m < 4; m++) {
            float v = acc[m][n] + bb;
            sH[(ty * 4 + m) * SH_LD + tx * 8 + n] = v > 0.f ? v : 0.f;
        }
    }

    // ATT = sigmoid(H @ A2 + ab2); scatter MSG*ATT
    mm_tile(sH, SH_LD, MSGD, A2, sW, acc, tid, tx, ty);
#pragma unroll
    for (int n = 0; n < 8; n++) {
        float bb = __ldg(&ab2[tx * 8 + n]);
#pragma unroll
        for (int m = 0; m < 4; m++) {
            float att = 1.f / (1.f + expf(-(acc[m][n] + bb)));
            float v = sM[(ty * 4 + m) * SH_LD + tx * 8 + n] * att;
            atomicAdd(&out_msg[(size_t)sDst[ty * 4 + m] * MSGD + tx * 8 + n], v);
        }
    }
}

// ---------------- generic GEMM: C[r, j0..j0+127] = A[r,:128] @ W + bias -----
// A: [Mrows x 128], W: [128 x 384] (row-major), grid.y selects 128-col tile.
__global__ void __launch_bounds__(THREADS) gemm_bias_kernel(
    const float* __restrict__ A,
    const float* __restrict__ W,
    const float* __restrict__ bias,
    float* __restrict__ C,
    int Mrows)
{
    __shared__ float sA[64 * SH_LD];
    __shared__ float sW[KC * 128];
    int tid = threadIdx.x, tx = tid & 15, ty = tid >> 4;
    int r0 = blockIdx.x * 64;
    int j0 = blockIdx.y * 128;

    for (int idx = tid; idx < 64 * DD; idx += THREADS) {
        int r = idx >> 7, k = idx & 127;
        sA[r * SH_LD + k] = (r0 + r < Mrows) ? A[(size_t)(r0 + r) * DD + k] : 0.f;
    }

    float acc[4][8];
#pragma unroll
    for (int m = 0; m < 4; m++)
#pragma unroll
        for (int n = 0; n < 8; n++) acc[m][n] = 0.f;

    for (int kc = 0; kc < DD; kc += KC) {
        __syncthreads();
        for (int i = tid; i < KC * 128; i += THREADS)
            sW[i] = W[(size_t)(kc + (i >> 7)) * 384 + j0 + (i & 127)];
        __syncthreads();
#pragma unroll 8
        for (int kk = 0; kk < KC; ++kk) {
            float a[4];
#pragma unroll
            for (int m = 0; m < 4; m++) a[m] = sA[(ty * 4 + m) * SH_LD + kc + kk];
            float4 bv0 = *(const float4*)&sW[kk * 128 + tx * 8];
            float4 bv1 = *(const float4*)&sW[kk * 128 + tx * 8 + 4];
            float b[8] = {bv0.x, bv0.y, bv0.z, bv0.w, bv1.x, bv1.y, bv1.z, bv1.w};
#pragma unroll
            for (int m = 0; m < 4; m++)
#pragma unroll
                for (int n = 0; n < 8; n++)
                    acc[m][n] = fmaf(a[m], b[n], acc[m][n]);
        }
    }

#pragma unroll
    for (int n = 0; n < 8; n++) {
        float bb = __ldg(&bias[j0 + tx * 8 + n]);
#pragma unroll
        for (int m = 0; m < 4; m++) {
            int r = r0 + ty * 4 + m;
            if (r < Mrows)
                C[(size_t)r * 384 + j0 + tx * 8 + n] = acc[m][n] + bb;
        }
    }
}

// ---------------- GRU elementwise combine --------------------------
__global__ void gru_combine_kernel(const float* __restrict__ gi,
                                   const float* __restrict__ gh,
                                   const float* __restrict__ h,
                                   float* __restrict__ out,
                                   int relu_flag)
{
    int idx = blockIdx.x * blockDim.x + threadIdx.x;
    if (idx >= NNODES * DD) return;
    int n = idx / DD, d = idx - n * DD;
    size_t base = (size_t)n * 3 * DD;
    float gir = gi[base + d], giz = gi[base + DD + d], gin = gi[base + 2 * DD + d];
    float ghr = gh[base + d], ghz = gh[base + DD + d], ghn = gh[base + 2 * DD + d];
    float hv = h[idx];
    float r = 1.f / (1.f + expf(-(gir + ghr)));
    float z = 1.f / (1.f + expf(-(giz + ghz)));
    float nn = tanhf(gin + r * ghn);
    float o = (1.f - z) * nn + z * hv;
    if (relu_flag) o = o > 0.f ? o : 0.f;
    out[idx] = o;
}

// ---------------- launch --------------------------------------------
extern "C" void kernel_launch(void* const* d_in, const int* in_sizes, int n_in,
                              void* d_out, int out_size)
{
    const float* node_feat  = (const float*)d_in[0];
    const int*   edge_index = (const int*)  d_in[1];
    const float* edge_feat  = (const float*)d_in[2];
    const float* W1  = (const float*)d_in[3];
    const float* b1  = (const float*)d_in[4];
    const float* W2  = (const float*)d_in[5];
    const float* b2  = (const float*)d_in[6];
    const float* A1  = (const float*)d_in[7];
    const float* ab1 = (const float*)d_in[8];
    const float* A2  = (const float*)d_in[9];
    const float* ab2 = (const float*)d_in[10];
    const float* Wih = (const float*)d_in[11];
    const float* bih = (const float*)d_in[12];
    const float* Whh = (const float*)d_in[13];
    const float* bhh = (const float*)d_in[14];

    const int* src = edge_index;
    const int* dst = edge_index + NEDGES;

    float *stateA, *stateB, *msg, *gi, *gh;
    cudaGetSymbolAddress((void**)&stateA, g_stateA);
    cudaGetSymbolAddress((void**)&stateB, g_stateB);
    cudaGetSymbolAddress((void**)&msg,    g_msg);
    cudaGetSymbolAddress((void**)&gi,     g_gi);
    cudaGetSymbolAddress((void**)&gh,     g_gh);

    size_t smem_edge = (size_t)(TILE_E * SX_LD + 2 * TILE_E * SH_LD + KC * 128) * sizeof(float);
    cudaFuncSetAttribute(edge_kernel, cudaFuncAttributeMaxDynamicSharedMemorySize, (int)smem_edge);

    const float* state = node_feat;
    float* bufs[2] = {stateA, stateB};
    int cur = 0;

    for (int ii = 0; ii < LL; ++ii) {
        for (int p = 0; p < PP; ++p) {
            cudaMemsetAsync(msg, 0, (size_t)NNODES * MSGD * sizeof(float));

            size_t wo1 = (size_t)ii * K1 * MSGD;
            size_t wo2 = (size_t)ii * MSGD * MSGD;
            size_t bo  = (size_t)ii * MSGD;
            edge_kernel<<<NEDGES / TILE_E, THREADS, smem_edge>>>(
                state, src, dst, edge_feat,
                W1 + wo1, b1 + bo, W2 + wo2, b2 + bo,
                A1 + wo1, ab1 + bo, A2 + wo2, ab2 + bo, msg);

            dim3 gg((NNODES + 63) / 64, 3);
            gemm_bias_kernel<<<gg, THREADS>>>(msg,   Wih + (size_t)ii * DD * 3 * DD,
                                              bih + (size_t)ii * 3 * DD, gi, NNODES);
            gemm_bias_kernel<<<gg, THREADS>>>(state, Whh + (size_t)ii * DD * 3 * DD,
                                              bhh + (size_t)ii * 3 * DD, gh, NNODES);

            bool last = (ii == LL - 1 && p == PP - 1);
            bool relu = (!last) && (p == PP - 1);   // layer-boundary relu
            float* outp = last ? (float*)d_out : bufs[cur];
            gru_combine_kernel<<<(NNODES * DD + THREADS - 1) / THREADS, THREADS>>>(
                gi, gh, state, outp, relu ? 1 : 0);
            state = outp;
            cur ^= 1;
        }
    }
}

// round 7
// speedup vs baseline: 1.0028x; 1.0028x over previous
#include <cuda_runtime.h>
#include <math.h>

// Problem constants
#define NNODES 50000
#define NEDGES 800000
#define DD     128
#define EE     32
#define MSGD   128
#define K1     160   // D + E
#define LL     2
#define PP     2

// Tiling
#define TILE_E  64
#define KC      32
#define THREADS 256

// Padded shared strides (avoid bank conflicts: 160%32==0, 128%32==0)
#define SX_LD 164
#define SH_LD 132

// -------- scratch (allocation-free: __device__ globals) ----------
__device__ float g_stateA[NNODES * DD];
__device__ float g_stateB[NNODES * DD];
__device__ float g_msg[NNODES * MSGD];
__device__ float g_gi[NNODES * 3 * DD];
__device__ float g_gh[NNODES * 3 * DD];

// ---------------- fused edge kernel -------------------------------
// One CTA = 64 edges. Computes:
//   X = [state[src]-state[dst], edge_feat]                (smem, 64x160)
//   H = relu(X@W1 + b1); MSG = H@W2 + b2                  (smem)
//   H = relu(X@A1 + ab1); ATT = sigmoid(H@A2 + ab2)
//   atomicAdd(out_msg[dst], MSG * ATT)
// Register tile per thread: 4 edges x 8 cols.

__device__ __forceinline__ void mm_tile(const float* sIn, int ldIn, int kdim,
                                        const float* __restrict__ gW, float* sW,
                                        float acc[4][8], int tid, int tx, int ty)
{
#pragma unroll
    for (int m = 0; m < 4; m++)
#pragma unroll
        for (int n = 0; n < 8; n++) acc[m][n] = 0.f;

    for (int kc = 0; kc < kdim; kc += KC) {
        __syncthreads();  // protect sW reuse + orders producer writes
#pragma unroll
        for (int i = tid; i < KC * 128; i += THREADS)
            sW[i] = gW[(size_t)(kc + (i >> 7)) * 128 + (i & 127)];
        __syncthreads();
#pragma unroll 8
        for (int kk = 0; kk < KC; ++kk) {
            float a[4];
#pragma unroll
            for (int m = 0; m < 4; m++) a[m] = sIn[(ty * 4 + m) * ldIn + kc + kk];
            float4 bv0 = *(const float4*)&sW[kk * 128 + tx * 8];
            float4 bv1 = *(const float4*)&sW[kk * 128 + tx * 8 + 4];
            float b[8] = {bv0.x, bv0.y, bv0.z, bv0.w, bv1.x, bv1.y, bv1.z, bv1.w};
#pragma unroll
            for (int m = 0; m < 4; m++)
#pragma unroll
                for (int n = 0; n < 8; n++)
                    acc[m][n] = fmaf(a[m], b[n], acc[m][n]);
        }
    }
}

__global__ void __launch_bounds__(THREADS) edge_kernel(
    const float* __restrict__ state,
    const int* __restrict__ src, const int* __restrict__ dst,
    const float* __restrict__ edge_feat,
    const float* __restrict__ W1, const float* __restrict__ b1,
    const float* __restrict__ W2, const float* __restrict__ b2,
    const float* __restrict__ A1, const float* __restrict__ ab1,
    const float* __restrict__ A2, const float* __restrict__ ab2,
    float* __restrict__ out_msg)
{
    extern __shared__ float sm[];
    float* sX = sm;                            // TILE_E * SX_LD
    float* sH = sX + TILE_E * SX_LD;           // TILE_E * SH_LD
    float* sM = sH + TILE_E * SH_LD;           // TILE_E * SH_LD
    float* sW = sM + TILE_E * SH_LD;           // KC * 128
    __shared__ int sSrc[TILE_E], sDst[TILE_E];

    int tid = threadIdx.x;
    int tx = tid & 15;   // col group: j = tx*8 .. tx*8+7
    int ty = tid >> 4;   // edge group: e = ty*4 .. ty*4+3
    int e0 = blockIdx.x * TILE_E;

    if (tid < TILE_E) { sSrc[tid] = src[e0 + tid]; sDst[tid] = dst[e0 + tid]; }
    __syncthreads();

    // Gather edge_input
    for (int idx = tid; idx < TILE_E * K1; idx += THREADS) {
        int e = idx / K1, k = idx - e * K1;
        float v;
        if (k < DD)
            v = state[(size_t)sSrc[e] * DD + k] - state[(size_t)sDst[e] * DD + k];
        else
            v = edge_feat[(size_t)(e0 + e) * EE + (k - DD)];
        sX[e * SX_LD + k] = v;
    }
    // (mm_tile begins with __syncthreads)

    float acc[4][8];

    // H = relu(X @ W1 + b1)
    mm_tile(sX, SX_LD, K1, W1, sW, acc, tid, tx, ty);
#pragma unroll
    for (int n = 0; n < 8; n++) {
        float bb = __ldg(&b1[tx * 8 + n]);
#pragma unroll
        for (int m = 0; m < 4; m++) {
            float v = acc[m][n] + bb;
            sH[(ty * 4 + m) * SH_LD + tx * 8 + n] = v > 0.f ? v : 0.f;
        }
    }

    // MSG = H @ W2 + b2
    mm_tile(sH, SH_LD, MSGD, W2, sW, acc, tid, tx, ty);
#pragma unroll
    for (int n = 0; n < 8; n++) {
        float bb = __ldg(&b2[tx * 8 + n]);
#pragma unroll
        for (int m = 0; m < 4; m++)
            sM[(ty * 4 + m) * SH_LD + tx * 8 + n] = acc[m][n] + bb;
    }

    // H = relu(X @ A1 + ab1)   (overwrites sH; safe via mm_tile's chunk syncs)
    mm_tile(sX, SX_LD, K1, A1, sW, acc, tid, tx, ty);
#pragma unroll
    for (int n = 0; n < 8; n++) {
        float bb = __ldg(&ab1[tx * 8 + n]);
#pragma unroll
        for (int m = 0; m < 4; m++) {
            float v = acc[m][n] + bb;
            sH[(ty * 4 + m) * SH_LD + tx * 8 + n] = v > 0.f ? v : 0.f;
        }
    }

    // ATT = sigmoid(H @ A2 + ab2); scatter MSG*ATT
    mm_tile(sH, SH_LD, MSGD, A2, sW, acc, tid, tx, ty);
#pragma unroll
    for (int n = 0; n < 8; n++) {
        float bb = __ldg(&ab2[tx * 8 + n]);
#pragma unroll
        for (int m = 0; m < 4; m++) {
            float att = 1.f / (1.f + expf(-(acc[m][n] + bb)));
            float v = sM[(ty * 4 + m) * SH_LD + tx * 8 + n] * att;
            atomicAdd(&out_msg[(size_t)sDst[ty * 4 + m] * MSGD + tx * 8 + n], v);
        }
    }
}

// ---------------- generic GEMM: C[r, j0..j0+127] = A[r,:128] @ W + bias -----
// A: [Mrows x 128], W: [128 x 384] (row-major), grid.y selects 128-col tile.
__global__ void __launch_bounds__(THREADS) gemm_bias_kernel(
    const float* __restrict__ A,
    const float* __restrict__ W,
    const float* __restrict__ bias,
    float* __restrict__ C,
    int Mrows)
{
    __shared__ float sA[64 * SH_LD];
    __shared__ float sW[KC * 128];
    int tid = threadIdx.x, tx = tid & 15, ty = tid >> 4;
    int r0 = blockIdx.x * 64;
    int j0 = blockIdx.y * 128;

    for (int idx = tid; idx < 64 * DD; idx += THREADS) {
        int r = idx >> 7, k = idx & 127;
        sA[r * SH_LD + k] = (r0 + r < Mrows) ? A[(size_t)(r0 + r) * DD + k] : 0.f;
    }

    float acc[4][8];
#pragma unroll
    for (int m = 0; m < 4; m++)
#pragma unroll
        for (int n = 0; n < 8; n++) acc[m][n] = 0.f;

    for (int kc = 0; kc < DD; kc += KC) {
        __syncthreads();
        for (int i = tid; i < KC * 128; i += THREADS)
            sW[i] = W[(size_t)(kc + (i >> 7)) * 384 + j0 + (i & 127)];
        __syncthreads();
#pragma unroll 8
        for (int kk = 0; kk < KC; ++kk) {
            float a[4];
#pragma unroll
            for (int m = 0; m < 4; m++) a[m] = sA[(ty * 4 + m) * SH_LD + kc + kk];
            float4 bv0 = *(const float4*)&sW[kk * 128 + tx * 8];
            float4 bv1 = *(const float4*)&sW[kk * 128 + tx * 8 + 4];
            float b[8] = {bv0.x, bv0.y, bv0.z, bv0.w, bv1.x, bv1.y, bv1.z, bv1.w};
#pragma unroll
            for (int m = 0; m < 4; m++)
#pragma unroll
                for (int n = 0; n < 8; n++)
                    acc[m][n] = fmaf(a[m], b[n], acc[m][n]);
        }
    }

#pragma unroll
    for (int n = 0; n < 8; n++) {
        float bb = __ldg(&bias[j0 + tx * 8 + n]);
#pragma unroll
        for (int m = 0; m < 4; m++) {
            int r = r0 + ty * 4 + m;
            if (r < Mrows)
                C[(size_t)r * 384 + j0 + tx * 8 + n] = acc[m][n] + bb;
        }
    }
}

// ---------------- GRU elementwise combine --------------------------
__global__ void gru_combine_kernel(const float* __restrict__ gi,
                                   const float* __restrict__ gh,
                                   const float* __restrict__ h,
                                   float* __restrict__ out,
                                   int relu_flag)
{
    int idx = blockIdx.x * blockDim.x + threadIdx.x;
    if (idx >= NNODES * DD) return;
    int n = idx / DD, d = idx - n * DD;
    size_t base = (size_t)n * 3 * DD;
    float gir = gi[base + d], giz = gi[base + DD + d], gin = gi[base + 2 * DD + d];
    float ghr = gh[base + d], ghz = gh[base + DD + d], ghn = gh[base + 2 * DD + d];
    float hv = h[idx];
    float r = 1.f / (1.f + expf(-(gir + ghr)));
    float z = 1.f / (1.f + expf(-(giz + ghz)));
    float nn = tanhf(gin + r * ghn);
    float o = (1.f - z) * nn + z * hv;
    if (relu_flag) o = o > 0.f ? o : 0.f;
    out[idx] = o;
}

// ---------------- launch --------------------------------------------
extern "C" void kernel_launch(void* const* d_in, const int* in_sizes, int n_in,
                              void* d_out, int out_size)
{
    const float* node_feat  = (const float*)d_in[0];
    const int*   edge_index = (const int*)  d_in[1];
    const float* edge_feat  = (const float*)d_in[2];
    const float* W1  = (const float*)d_in[3];
    const float* b1  = (const float*)d_in[4];
    const float* W2  = (const float*)d_in[5];
    const float* b2  = (const float*)d_in[6];
    const float* A1  = (const float*)d_in[7];
    const float* ab1 = (const float*)d_in[8];
    const float* A2  = (const float*)d_in[9];
    const float* ab2 = (const float*)d_in[10];
    const float* Wih = (const float*)d_in[11];
    const float* bih = (const float*)d_in[12];
    const float* Whh = (const float*)d_in[13];
    const float* bhh = (const float*)d_in[14];

    const int* src = edge_index;
    const int* dst = edge_index + NEDGES;

    float *stateA, *stateB, *msg, *gi, *gh;
    cudaGetSymbolAddress((void**)&stateA, g_stateA);
    cudaGetSymbolAddress((void**)&stateB, g_stateB);
    cudaGetSymbolAddress((void**)&msg,    g_msg);
    cudaGetSymbolAddress((void**)&gi,     g_gi);
    cudaGetSymbolAddress((void**)&gh,     g_gh);

    size_t smem_edge = (size_t)(TILE_E * SX_LD + 2 * TILE_E * SH_LD + KC * 128) * sizeof(float);
    cudaFuncSetAttribute(edge_kernel, cudaFuncAttributeMaxDynamicSharedMemorySize, (int)smem_edge);

    const float* state = node_feat;
    float* bufs[2] = {stateA, stateB};
    int cur = 0;

    for (int ii = 0; ii < LL; ++ii) {
        for (int p = 0; p < PP; ++p) {
            cudaMemsetAsync(msg, 0, (size_t)NNODES * MSGD * sizeof(float));

            size_t wo1 = (size_t)ii * K1 * MSGD;
            size_t wo2 = (size_t)ii * MSGD * MSGD;
            size_t bo  = (size_t)ii * MSGD;
            edge_kernel<<<NEDGES / TILE_E, THREADS, smem_edge>>>(
                state, src, dst, edge_feat,
                W1 + wo1, b1 + bo, W2 + wo2, b2 + bo,
                A1 + wo1, ab1 + bo, A2 + wo2, ab2 + bo, msg);

            dim3 gg((NNODES + 63) / 64, 3);
            gemm_bias_kernel<<<gg, THREADS>>>(msg,   Wih + (size_t)ii * DD * 3 * DD,
                                              bih + (size_t)ii * 3 * DD, gi, NNODES);
            gemm_bias_kernel<<<gg, THREADS>>>(state, Whh + (size_t)ii * DD * 3 * DD,
                                              bhh + (size_t)ii * 3 * DD, gh, NNODES);

            bool last = (ii == LL - 1 && p == PP - 1);
            bool relu = (!last) && (p == PP - 1);   // layer-boundary relu
            float* outp = last ? (float*)d_out : bufs[cur];
            gru_combine_kernel<<<(NNODES * DD + THREADS - 1) / THREADS, THREADS>>>(
                gi, gh, state, outp, relu ? 1 : 0);
            state = outp;
            cur ^= 1;
        }
    }
}

// round 9
// speedup vs baseline: 1.0035x; 1.0008x over previous
#include <cuda_runtime.h>
#include <math.h>

// Problem constants
#define NNODES 50000
#define NEDGES 800000
#define DD     128
#define EE     32
#define MSGD   128
#define K1     160   // D + E
#define LL     2
#define PP     2

// Tiling
#define TILE_E  64
#define KC      32
#define THREADS 256

// Padded shared strides (avoid bank conflicts: 160%32==0, 128%32==0)
#define SX_LD 164
#define SH_LD 132

// -------- scratch (allocation-free: __device__ globals) ----------
__device__ float g_stateA[NNODES * DD];
__device__ float g_stateB[NNODES * DD];
__device__ float g_msg[NNODES * MSGD];
__device__ float g_gi[NNODES * 3 * DD];
__device__ float g_gh[NNODES * 3 * DD];

// ---------------- fused edge kernel -------------------------------
// One CTA = 64 edges. Computes:
//   X = [state[src]-state[dst], edge_feat]                (smem, 64x160)
//   H = relu(X@W1 + b1); MSG = H@W2 + b2                  (smem)
//   H = relu(X@A1 + ab1); ATT = sigmoid(H@A2 + ab2)
//   atomicAdd(out_msg[dst], MSG * ATT)
// Register tile per thread: 4 edges x 8 cols.

__device__ __forceinline__ void mm_tile(const float* sIn, int ldIn, int kdim,
                                        const float* __restrict__ gW, float* sW,
                                        float acc[4][8], int tid, int tx, int ty)
{
#pragma unroll
    for (int m = 0; m < 4; m++)
#pragma unroll
        for (int n = 0; n < 8; n++) acc[m][n] = 0.f;

    for (int kc = 0; kc < kdim; kc += KC) {
        __syncthreads();  // protect sW reuse + orders producer writes
#pragma unroll
        for (int i = tid; i < KC * 128; i += THREADS)
            sW[i] = gW[(size_t)(kc + (i >> 7)) * 128 + (i & 127)];
        __syncthreads();
#pragma unroll 8
        for (int kk = 0; kk < KC; ++kk) {
            float a[4];
#pragma unroll
            for (int m = 0; m < 4; m++) a[m] = sIn[(ty * 4 + m) * ldIn + kc + kk];
            float4 bv0 = *(const float4*)&sW[kk * 128 + tx * 8];
            float4 bv1 = *(const float4*)&sW[kk * 128 + tx * 8 + 4];
            float b[8] = {bv0.x, bv0.y, bv0.z, bv0.w, bv1.x, bv1.y, bv1.z, bv1.w};
#pragma unroll
            for (int m = 0; m < 4; m++)
#pragma unroll
                for (int n = 0; n < 8; n++)
                    acc[m][n] = fmaf(a[m], b[n], acc[m][n]);
        }
    }
}

__global__ void __launch_bounds__(THREADS) edge_kernel(
    const float* __restrict__ state,
    const int* __restrict__ src, const int* __restrict__ dst,
    const float* __restrict__ edge_feat,
    const float* __restrict__ W1, const float* __restrict__ b1,
    const float* __restrict__ W2, const float* __restrict__ b2,
    const float* __restrict__ A1, const float* __restrict__ ab1,
    const float* __restrict__ A2, const float* __restrict__ ab2,
    float* __restrict__ out_msg)
{
    extern __shared__ float sm[];
    float* sX = sm;                            // TILE_E * SX_LD
    float* sH = sX + TILE_E * SX_LD;           // TILE_E * SH_LD
    float* sM = sH + TILE_E * SH_LD;           // TILE_E * SH_LD
    float* sW = sM + TILE_E * SH_LD;           // KC * 128
    __shared__ int sSrc[TILE_E], sDst[TILE_E];

    int tid = threadIdx.x;
    int tx = tid & 15;   // col group: j = tx*8 .. tx*8+7
    int ty = tid >> 4;   // edge group: e = ty*4 .. ty*4+3
    int e0 = blockIdx.x * TILE_E;

    if (tid < TILE_E) { sSrc[tid] = src[e0 + tid]; sDst[tid] = dst[e0 + tid]; }
    __syncthreads();

    // Gather edge_input
    for (int idx = tid; idx < TILE_E * K1; idx += THREADS) {
        int e = idx / K1, k = idx - e * K1;
        float v;
        if (k < DD)
            v = state[(size_t)sSrc[e] * DD + k] - state[(size_t)sDst[e] * DD + k];
        else
            v = edge_feat[(size_t)(e0 + e) * EE + (k - DD)];
        sX[e * SX_LD + k] = v;
    }
    // (mm_tile begins with __syncthreads)

    float acc[4][8];

    // H = relu(X @ W1 + b1)
    mm_tile(sX, SX_LD, K1, W1, sW, acc, tid, tx, ty);
#pragma unroll
    for (int n = 0; n < 8; n++) {
        float bb = __ldg(&b1[tx * 8 + n]);
#pragma unroll
        for (int m = 0; m < 4; m++) {
            float v = acc[m][n] + bb;
            sH[(ty * 4 + m) * SH_LD + tx * 8 + n] = v > 0.f ? v : 0.f;
        }
    }

    // MSG = H @ W2 + b2
    mm_tile(sH, SH_LD, MSGD, W2, sW, acc, tid, tx, ty);
#pragma unroll
    for (int n = 0; n < 8; n++) {
        float bb = __ldg(&b2[tx * 8 + n]);
#pragma unroll
        for (int m = 0; m < 4; m++)
            sM[(ty * 4 + m) * SH_LD + tx * 8 + n] = acc[m][n] + bb;
    }

    // H = relu(X @ A1 + ab1)   (overwrites sH; safe via mm_tile's chunk syncs)
    mm_tile(sX, SX_LD, K1, A1, sW, acc, tid, tx, ty);
#pragma unroll
    for (int n = 0; n < 8; n++) {
        float bb = __ldg(&ab1[tx * 8 + n]);
#pragma unroll
        for (int m = 0; m < 4; m++) {
            float v = acc[m][n] + bb;
            sH[(ty * 4 + m) * SH_LD + tx * 8 + n] = v > 0.f ? v : 0.f;
        }
    }

    // ATT = sigmoid(H @ A2 + ab2); scatter MSG*ATT
    mm_tile(sH, SH_LD, MSGD, A2, sW, acc, tid, tx, ty);
#pragma unroll
    for (int n = 0; n < 8; n++) {
        float bb = __ldg(&ab2[tx * 8 + n]);
#pragma unroll
        for (int m = 0; m < 4; m++) {
            float att = 1.f / (1.f + expf(-(acc[m][n] + bb)));
            float v = sM[(ty * 4 + m) * SH_LD + tx * 8 + n] * att;
            atomicAdd(&out_msg[(size_t)sDst[ty * 4 + m] * MSGD + tx * 8 + n], v);
        }
    }
}

// ---------------- generic GEMM: C[r, j0..j0+127] = A[r,:128] @ W + bias -----
// A: [Mrows x 128], W: [128 x 384] (row-major), grid.y selects 128-col tile.
__global__ void __launch_bounds__(THREADS) gemm_bias_kernel(
    const float* __restrict__ A,
    const float* __restrict__ W,
    const float* __restrict__ bias,
    float* __restrict__ C,
    int Mrows)
{
    __shared__ float sA[64 * SH_LD];
    __shared__ float sW[KC * 128];
    int tid = threadIdx.x, tx = tid & 15, ty = tid >> 4;
    int r0 = blockIdx.x * 64;
    int j0 = blockIdx.y * 128;

    for (int idx = tid; idx < 64 * DD; idx += THREADS) {
        int r = idx >> 7, k = idx & 127;
        sA[r * SH_LD + k] = (r0 + r < Mrows) ? A[(size_t)(r0 + r) * DD + k] : 0.f;
    }

    float acc[4][8];
#pragma unroll
    for (int m = 0; m < 4; m++)
#pragma unroll
        for (int n = 0; n < 8; n++) acc[m][n] = 0.f;

    for (int kc = 0; kc < DD; kc += KC) {
        __syncthreads();
        for (int i = tid; i < KC * 128; i += THREADS)
            sW[i] = W[(size_t)(kc + (i >> 7)) * 384 + j0 + (i & 127)];
        __syncthreads();
#pragma unroll 8
        for (int kk = 0; kk < KC; ++kk) {
            float a[4];
#pragma unroll
            for (int m = 0; m < 4; m++) a[m] = sA[(ty * 4 + m) * SH_LD + kc + kk];
            float4 bv0 = *(const float4*)&sW[kk * 128 + tx * 8];
            float4 bv1 = *(const float4*)&sW[kk * 128 + tx * 8 + 4];
            float b[8] = {bv0.x, bv0.y, bv0.z, bv0.w, bv1.x, bv1.y, bv1.z, bv1.w};
#pragma unroll
            for (int m = 0; m < 4; m++)
#pragma unroll
                for (int n = 0; n < 8; n++)
                    acc[m][n] = fmaf(a[m], b[n], acc[m][n]);
        }
    }

#pragma unroll
    for (int n = 0; n < 8; n++) {
        float bb = __ldg(&bias[j0 + tx * 8 + n]);
#pragma unroll
        for (int m = 0; m < 4; m++) {
            int r = r0 + ty * 4 + m;
            if (r < Mrows)
                C[(size_t)r * 384 + j0 + tx * 8 + n] = acc[m][n] + bb;
        }
    }
}

// ---------------- GRU elementwise combine --------------------------
__global__ void gru_combine_kernel(const float* __restrict__ gi,
                                   const float* __restrict__ gh,
                                   const float* __restrict__ h,
                                   float* __restrict__ out,
                                   int relu_flag)
{
    int idx = blockIdx.x * blockDim.x + threadIdx.x;
    if (idx >= NNODES * DD) return;
    int n = idx / DD, d = idx - n * DD;
    size_t base = (size_t)n * 3 * DD;
    float gir = gi[base + d], giz = gi[base + DD + d], gin = gi[base + 2 * DD + d];
    float ghr = gh[base + d], ghz = gh[base + DD + d], ghn = gh[base + 2 * DD + d];
    float hv = h[idx];
    float r = 1.f / (1.f + expf(-(gir + ghr)));
    float z = 1.f / (1.f + expf(-(giz + ghz)));
    float nn = tanhf(gin + r * ghn);
    float o = (1.f - z) * nn + z * hv;
    if (relu_flag) o = o > 0.f ? o : 0.f;
    out[idx] = o;
}

// ---------------- launch --------------------------------------------
extern "C" void kernel_launch(void* const* d_in, const int* in_sizes, int n_in,
                              void* d_out, int out_size)
{
    const float* node_feat  = (const float*)d_in[0];
    const int*   edge_index = (const int*)  d_in[1];
    const float* edge_feat  = (const float*)d_in[2];
    const float* W1  = (const float*)d_in[3];
    const float* b1  = (const float*)d_in[4];
    const float* W2  = (const float*)d_in[5];
    const float* b2  = (const float*)d_in[6];
    const float* A1  = (const float*)d_in[7];
    const float* ab1 = (const float*)d_in[8];
    const float* A2  = (const float*)d_in[9];
    const float* ab2 = (const float*)d_in[10];
    const float* Wih = (const float*)d_in[11];
    const float* bih = (const float*)d_in[12];
    const float* Whh = (const float*)d_in[13];
    const float* bhh = (const float*)d_in[14];

    const int* src = edge_index;
    const int* dst = edge_index + NEDGES;

    float *stateA, *stateB, *msg, *gi, *gh;
    cudaGetSymbolAddress((void**)&stateA, g_stateA);
    cudaGetSymbolAddress((void**)&stateB, g_stateB);
    cudaGetSymbolAddress((void**)&msg,    g_msg);
    cudaGetSymbolAddress((void**)&gi,     g_gi);
    cudaGetSymbolAddress((void**)&gh,     g_gh);

    size_t smem_edge = (size_t)(TILE_E * SX_LD + 2 * TILE_E * SH_LD + KC * 128) * sizeof(float);
    cudaFuncSetAttribute(edge_kernel, cudaFuncAttributeMaxDynamicSharedMemorySize, (int)smem_edge);

    const float* state = node_feat;
    float* bufs[2] = {stateA, stateB};
    int cur = 0;

    for (int ii = 0; ii < LL; ++ii) {
        for (int p = 0; p < PP; ++p) {
            cudaMemsetAsync(msg, 0, (size_t)NNODES * MSGD * sizeof(float));

            size_t wo1 = (size_t)ii * K1 * MSGD;
            size_t wo2 = (size_t)ii * MSGD * MSGD;
            size_t bo  = (size_t)ii * MSGD;
            edge_kernel<<<NEDGES / TILE_E, THREADS, smem_edge>>>(
                state, src, dst, edge_feat,
                W1 + wo1, b1 + bo, W2 + wo2, b2 + bo,
                A1 + wo1, ab1 + bo, A2 + wo2, ab2 + bo, msg);

            dim3 gg((NNODES + 63) / 64, 3);
            gemm_bias_kernel<<<gg, THREADS>>>(msg,   Wih + (size_t)ii * DD * 3 * DD,
                                              bih + (size_t)ii * 3 * DD, gi, NNODES);
            gemm_bias_kernel<<<gg, THREADS>>>(state, Whh + (size_t)ii * DD * 3 * DD,
                                              bhh + (size_t)ii * 3 * DD, gh, NNODES);

            bool last = (ii == LL - 1 && p == PP - 1);
            bool relu = (!last) && (p == PP - 1);   // layer-boundary relu
            float* outp = last ? (float*)d_out : bufs[cur];
            gru_combine_kernel<<<(NNODES * DD + THREADS - 1) / THREADS, THREADS>>>(
                gi, gh, state, outp, relu ? 1 : 0);
            state = outp;
            cur ^= 1;
        }
    }
}

// round 14
// speedup vs baseline: 1.6226x; 1.6169x over previous
#include <cuda_runtime.h>
#include <math.h>

// Problem constants
#define NNODES 50000
#define NEDGES 800000
#define DD     128
#define EE     32
#define MSGD   128
#define K1     160   // D + E
#define LL     2
#define PP     2

// Edge-kernel tiling: 128 edges/CTA, 256 threads, 8x8 per-thread tile (f32x2 packed)
#define TILE_E  128
#define KC      32
#define THREADS 256

// Legacy stride for gemm_bias kernel
#define SH_LD 132

// -------- scratch (allocation-free: __device__ globals) ----------
__device__ float g_stateA[NNODES * DD];
__device__ float g_stateB[NNODES * DD];
__device__ float g_msg[NNODES * MSGD];
__device__ float g_gi[NNODES * 3 * DD];
__device__ float g_gh[NNODES * 3 * DD];

// ---------------- packed f32x2 helpers ----------------------------
#define PACK2(d, lo, hi) \
    asm("mov.b64 %0, {%1, %2};" : "=l"(d) : "f"(lo), "f"(hi))
#define UNPACK2(lo, hi, s) \
    asm("mov.b64 {%0, %1}, %2;" : "=f"(lo), "=f"(hi) : "l"(s))
#define FMA2(d, a, b) \
    asm("fma.rn.f32x2 %0, %1, %2, %0;" : "+l"(d) : "l"(a), "l"(b))

// ---------------- packed 8x8 MM tile -------------------------------
// acc[m][p] holds cols (tx*8+2p, tx*8+2p+1) for edge row0+m, packed f32x2.
__device__ __forceinline__ void mm_tile8(const float* sIn, int ldIn, int kdim,
                                         const float* __restrict__ gW, float* sW,
                                         unsigned long long acc[8][4],
                                         int tid, int tx, int ty)
{
#pragma unroll
    for (int m = 0; m < 8; m++)
#pragma unroll
        for (int p = 0; p < 4; p++) acc[m][p] = 0ull;

    const int row0 = ty * 8;
    for (int kc = 0; kc < kdim; kc += KC) {
        __syncthreads();  // protect sW reuse + order producer writes
        const float4* gsrc = (const float4*)(gW + (size_t)kc * 128);  // contiguous chunk
#pragma unroll
        for (int i = tid; i < KC * 128 / 4; i += THREADS)
            ((float4*)sW)[i] = gsrc[i];
        __syncthreads();
#pragma unroll
        for (int kk = 0; kk < KC; kk += 4) {
            float4 a4[8];
#pragma unroll
            for (int m = 0; m < 8; m++)
                a4[m] = *(const float4*)&sIn[(row0 + m) * ldIn + kc + kk];
#pragma unroll
            for (int j = 0; j < 4; j++) {
                const ulonglong2* bp = (const ulonglong2*)&sW[(kk + j) * 128 + tx * 8];
                ulonglong2 bq0 = bp[0];
                ulonglong2 bq1 = bp[1];
#pragma unroll
                for (int m = 0; m < 8; m++) {
                    float av = (j == 0) ? a4[m].x : (j == 1) ? a4[m].y
                             : (j == 2) ? a4[m].z : a4[m].w;
                    unsigned long long aa;
                    PACK2(aa, av, av);
                    FMA2(acc[m][0], aa, bq0.x);
                    FMA2(acc[m][1], aa, bq0.y);
                    FMA2(acc[m][2], aa, bq1.x);
                    FMA2(acc[m][3], aa, bq1.y);
                }
            }
        }
    }
}

// ---------------- fused edge kernel -------------------------------
// One CTA = 128 edges. X = [state[src]-state[dst], edge_feat];
// MSG = relu(X@W1+b1)@W2+b2; ATT = sigmoid(relu(X@A1+ab1)@A2+ab2);
// atomicAdd(out_msg[dst], MSG*ATT).
__global__ void __launch_bounds__(THREADS, 1) edge_kernel(
    const float* __restrict__ state,
    const int* __restrict__ src, const int* __restrict__ dst,
    const float* __restrict__ edge_feat,
    const float* __restrict__ W1, const float* __restrict__ b1,
    const float* __restrict__ W2, const float* __restrict__ b2,
    const float* __restrict__ A1, const float* __restrict__ ab1,
    const float* __restrict__ A2, const float* __restrict__ ab2,
    float* __restrict__ out_msg)
{
    extern __shared__ float sm[];
    float* sX = sm;                          // TILE_E * 160
    float* sH = sX + TILE_E * K1;            // TILE_E * 128
    float* sM = sH + TILE_E * MSGD;          // TILE_E * 128
    float* sW = sM + TILE_E * MSGD;          // KC * 128
    __shared__ int sSrc[TILE_E], sDst[TILE_E];

    int tid = threadIdx.x;
    int tx = tid & 15;    // col group: cols tx*8 .. tx*8+7
    int ty = tid >> 4;    // edge group: edges ty*8 .. ty*8+7
    int e0 = blockIdx.x * TILE_E;

    if (tid < TILE_E) { sSrc[tid] = src[e0 + tid]; sDst[tid] = dst[e0 + tid]; }
    __syncthreads();

    // Gather edge_input (vectorized float4: 40 float4 per edge = 32 diff + 8 feat)
    for (int idx = tid; idx < TILE_E * 40; idx += THREADS) {
        int e = idx / 40, q = idx - e * 40;
        float4 v;
        if (q < 32) {
            float4 a = ((const float4*)&state[(size_t)sSrc[e] * DD])[q];
            float4 b = ((const float4*)&state[(size_t)sDst[e] * DD])[q];
            v = make_float4(a.x - b.x, a.y - b.y, a.z - b.z, a.w - b.w);
        } else {
            v = ((const float4*)&edge_feat[(size_t)(e0 + e) * EE])[q - 32];
        }
        *(float4*)&sX[e * K1 + q * 4] = v;
    }
    // (mm_tile8 begins with __syncthreads)

    unsigned long long acc[8][4];

    // H = relu(X @ W1 + b1)
    mm_tile8(sX, K1, K1, W1, sW, acc, tid, tx, ty);
#pragma unroll
    for (int p = 0; p < 4; p++) {
        float blo = __ldg(&b1[tx * 8 + 2 * p]);
        float bhi = __ldg(&b1[tx * 8 + 2 * p + 1]);
#pragma unroll
        for (int m = 0; m < 8; m++) {
            float lo, hi;
            UNPACK2(lo, hi, acc[m][p]);
            lo += blo; hi += bhi;
            lo = lo > 0.f ? lo : 0.f;
            hi = hi > 0.f ? hi : 0.f;
            *(float2*)&sH[(ty * 8 + m) * MSGD + tx * 8 + 2 * p] = make_float2(lo, hi);
        }
    }

    // MSG = H @ W2 + b2
    mm_tile8(sH, MSGD, MSGD, W2, sW, acc, tid, tx, ty);
#pragma unroll
    for (int p = 0; p < 4; p++) {
        float blo = __ldg(&b2[tx * 8 + 2 * p]);
        float bhi = __ldg(&b2[tx * 8 + 2 * p + 1]);
#pragma unroll
        for (int m = 0; m < 8; m++) {
            float lo, hi;
            UNPACK2(lo, hi, acc[m][p]);
            *(float2*)&sM[(ty * 8 + m) * MSGD + tx * 8 + 2 * p] =
                make_float2(lo + blo, hi + bhi);
        }
    }

    // H = relu(X @ A1 + ab1)   (overwrites sH; mm_tile8's syncs order it)
    mm_tile8(sX, K1, K1, A1, sW, acc, tid, tx, ty);
#pragma unroll
    for (int p = 0; p < 4; p++) {
        float blo = __ldg(&ab1[tx * 8 + 2 * p]);
        float bhi = __ldg(&ab1[tx * 8 + 2 * p + 1]);
#pragma unroll
        for (int m = 0; m < 8; m++) {
            float lo, hi;
            UNPACK2(lo, hi, acc[m][p]);
            lo += blo; hi += bhi;
            lo = lo > 0.f ? lo : 0.f;
            hi = hi > 0.f ? hi : 0.f;
            *(float2*)&sH[(ty * 8 + m) * MSGD + tx * 8 + 2 * p] = make_float2(lo, hi);
        }
    }

    // ATT = sigmoid(H @ A2 + ab2); scatter MSG*ATT
    mm_tile8(sH, MSGD, MSGD, A2, sW, acc, tid, tx, ty);
#pragma unroll
    for (int p = 0; p < 4; p++) {
        float blo = __ldg(&ab2[tx * 8 + 2 * p]);
        float bhi = __ldg(&ab2[tx * 8 + 2 * p + 1]);
#pragma unroll
        for (int m = 0; m < 8; m++) {
            float lo, hi;
            UNPACK2(lo, hi, acc[m][p]);
            float att_lo = 1.f / (1.f + expf(-(lo + blo)));
            float att_hi = 1.f / (1.f + expf(-(hi + bhi)));
            float2 mv = *(const float2*)&sM[(ty * 8 + m) * MSGD + tx * 8 + 2 * p];
            float* dp = &out_msg[(size_t)sDst[ty * 8 + m] * MSGD + tx * 8 + 2 * p];
            atomicAdd(dp,     mv.x * att_lo);
            atomicAdd(dp + 1, mv.y * att_hi);
        }
    }
}

// ---------------- generic GEMM: C[r, j0..j0+127] = A[r,:128] @ W + bias -----
__global__ void __launch_bounds__(THREADS) gemm_bias_kernel(
    const float* __restrict__ A,
    const float* __restrict__ W,
    const float* __restrict__ bias,
    float* __restrict__ C,
    int Mrows)
{
    __shared__ float sA[64 * SH_LD];
    __shared__ float sW[KC * 128];
    int tid = threadIdx.x, tx = tid & 15, ty = tid >> 4;
    int r0 = blockIdx.x * 64;
    int j0 = blockIdx.y * 128;

    for (int idx = tid; idx < 64 * DD; idx += THREADS) {
        int r = idx >> 7, k = idx & 127;
        sA[r * SH_LD + k] = (r0 + r < Mrows) ? A[(size_t)(r0 + r) * DD + k] : 0.f;
    }

    float acc[4][8];
#pragma unroll
    for (int m = 0; m < 4; m++)
#pragma unroll
        for (int n = 0; n < 8; n++) acc[m][n] = 0.f;

    for (int kc = 0; kc < DD; kc += KC) {
        __syncthreads();
        for (int i = tid; i < KC * 128; i += THREADS)
            sW[i] = W[(size_t)(kc + (i >> 7)) * 384 + j0 + (i & 127)];
        __syncthreads();
#pragma unroll 8
        for (int kk = 0; kk < KC; ++kk) {
            float a[4];
#pragma unroll
            for (int m = 0; m < 4; m++) a[m] = sA[(ty * 4 + m) * SH_LD + kc + kk];
            float4 bv0 = *(const float4*)&sW[kk * 128 + tx * 8];
            float4 bv1 = *(const float4*)&sW[kk * 128 + tx * 8 + 4];
            float b[8] = {bv0.x, bv0.y, bv0.z, bv0.w, bv1.x, bv1.y, bv1.z, bv1.w};
#pragma unroll
            for (int m = 0; m < 4; m++)
#pragma unroll
                for (int n = 0; n < 8; n++)
                    acc[m][n] = fmaf(a[m], b[n], acc[m][n]);
        }
    }

#pragma unroll
    for (int n = 0; n < 8; n++) {
        float bb = __ldg(&bias[j0 + tx * 8 + n]);
#pragma unroll
        for (int m = 0; m < 4; m++) {
            int r = r0 + ty * 4 + m;
            if (r < Mrows)
                C[(size_t)r * 384 + j0 + tx * 8 + n] = acc[m][n] + bb;
        }
    }
}

// ---------------- GRU elementwise combine --------------------------
__global__ void gru_combine_kernel(const float* __restrict__ gi,
                                   const float* __restrict__ gh,
                                   const float* __restrict__ h,
                                   float* __restrict__ out,
                                   int relu_flag)
{
    int idx = blockIdx.x * blockDim.x + threadIdx.x;
    if (idx >= NNODES * DD) return;
    int n = idx / DD, d = idx - n * DD;
    size_t base = (size_t)n * 3 * DD;
    float gir = gi[base + d], giz = gi[base + DD + d], gin = gi[base + 2 * DD + d];
    float ghr = gh[base + d], ghz = gh[base + DD + d], ghn = gh[base + 2 * DD + d];
    float hv = h[idx];
    float r = 1.f / (1.f + expf(-(gir + ghr)));
    float z = 1.f / (1.f + expf(-(giz + ghz)));
    float nn = tanhf(gin + r * ghn);
    float o = (1.f - z) * nn + z * hv;
    if (relu_flag) o = o > 0.f ? o : 0.f;
    out[idx] = o;
}

// ---------------- launch --------------------------------------------
extern "C" void kernel_launch(void* const* d_in, const int* in_sizes, int n_in,
                              void* d_out, int out_size)
{
    const float* node_feat  = (const float*)d_in[0];
    const int*   edge_index = (const int*)  d_in[1];
    const float* edge_feat  = (const float*)d_in[2];
    const float* W1  = (const float*)d_in[3];
    const float* b1  = (const float*)d_in[4];
    const float* W2  = (const float*)d_in[5];
    const float* b2  = (const float*)d_in[6];
    const float* A1  = (const float*)d_in[7];
    const float* ab1 = (const float*)d_in[8];
    const float* A2  = (const float*)d_in[9];
    const float* ab2 = (const float*)d_in[10];
    const float* Wih = (const float*)d_in[11];
    const float* bih = (const float*)d_in[12];
    const float* Whh = (const float*)d_in[13];
    const float* bhh = (const float*)d_in[14];

    const int* src = edge_index;
    const int* dst = edge_index + NEDGES;

    float *stateA, *stateB, *msg, *gi, *gh;
    cudaGetSymbolAddress((void**)&stateA, g_stateA);
    cudaGetSymbolAddress((void**)&stateB, g_stateB);
    cudaGetSymbolAddress((void**)&msg,    g_msg);
    cudaGetSymbolAddress((void**)&gi,     g_gi);
    cudaGetSymbolAddress((void**)&gh,     g_gh);

    // sX(128x160) + sH(128x128) + sM(128x128) + sW(32x128) floats = 229376 B
    size_t smem_edge = (size_t)(TILE_E * K1 + 2 * TILE_E * MSGD + KC * 128) * sizeof(float);
    cudaFuncSetAttribute(edge_kernel, cudaFuncAttributeMaxDynamicSharedMemorySize, (int)smem_edge);

    const float* state = node_feat;
    float* bufs[2] = {stateA, stateB};
    int cur = 0;

    for (int ii = 0; ii < LL; ++ii) {
        for (int p = 0; p < PP; ++p) {
            cudaMemsetAsync(msg, 0, (size_t)NNODES * MSGD * sizeof(float));

            size_t wo1 = (size_t)ii * K1 * MSGD;
            size_t wo2 = (size_t)ii * MSGD * MSGD;
            size_t bo  = (size_t)ii * MSGD;
            edge_kernel<<<NEDGES / TILE_E, THREADS, smem_edge>>>(
                state, src, dst, edge_feat,
                W1 + wo1, b1 + bo, W2 + wo2, b2 + bo,
                A1 + wo1, ab1 + bo, A2 + wo2, ab2 + bo, msg);

            dim3 gg((NNODES + 63) / 64, 3);
            gemm_bias_kernel<<<gg, THREADS>>>(msg,   Wih + (size_t)ii * DD * 3 * DD,
                                              bih + (size_t)ii * 3 * DD, gi, NNODES);
            gemm_bias_kernel<<<gg, THREADS>>>(state, Whh + (size_t)ii * DD * 3 * DD,
                                              bhh + (size_t)ii * 3 * DD, gh, NNODES);

            bool last = (ii == LL - 1 && p == PP - 1);
            bool relu = (!last) && (p == PP - 1);   // layer-boundary relu
            float* outp = last ? (float*)d_out : bufs[cur];
            gru_combine_kernel<<<(NNODES * DD + THREADS - 1) / THREADS, THREADS>>>(
                gi, gh, state, outp, relu ? 1 : 0);
            state = outp;
            cur ^= 1;
        }
    }
}